// round 1
// baseline (speedup 1.0000x reference)
#include <cuda_runtime.h>
#include <math.h>

// Problem constants (from reference): N=100000 nodes, IN=256, H=4, D=64, H*D=256
#define N_MAX 100000
#define KDIM 256         // in_feats
#define HD   256         // H*D output feats per node
#define NHEAD 4

typedef unsigned long long ull;

// ---------------- scratch (device globals; no cudaMalloc allowed) ----------
__device__ float g_feat_src[(size_t)N_MAX * HD];   // 102.4 MB
__device__ float g_el[(size_t)N_MAX * NHEAD];
__device__ float g_er[(size_t)N_MAX * NHEAD];

// ---------------- packed f32x2 helpers (Blackwell PTX) ---------------------
__device__ __forceinline__ ull dup2(float x) {
    ull r;
    asm("mov.b64 %0, {%1, %1};" : "=l"(r) : "f"(x));
    return r;
}
__device__ __forceinline__ void fma2(ull& d, ull a, ull b) {
    asm("fma.rn.f32x2 %0, %1, %2, %0;" : "+l"(d) : "l"(a), "l"(b));
}
__device__ __forceinline__ float2 unpack2(ull v) {
    float2 r;
    asm("mov.b64 {%0, %1}, %2;" : "=f"(r.x), "=f"(r.y) : "l"(v));
    return r;
}

// ---------------- K1: feat_src = feat @ W^T  (C[m,o] = sum_k A[m,k]*W[o,k]) -
#define BM 64
#define BN 64
#define BK 16
#define SPAD 4

__global__ __launch_bounds__(256) void gemm_kernel(
    const float* __restrict__ A, const float* __restrict__ Wm, int M)
{
    __shared__ __align__(16) float As[BK][BM + SPAD];
    __shared__ __align__(16) float Bs[BK][BN + SPAD];

    const int tid = threadIdx.x;
    const int m0 = blockIdx.x * BM;
    const int o0 = blockIdx.y * BN;
    const int ty = tid >> 4;     // 0..15 : row group
    const int tx = tid & 15;     // 0..15 : col group
    const int lr = tid >> 2;     // 0..63 : tile row for loads
    const int lq = tid & 3;      // 0..3  : float4 index along K

    ull acc[4][2];
#pragma unroll
    for (int i = 0; i < 4; i++) { acc[i][0] = 0ull; acc[i][1] = 0ull; }

    for (int k0 = 0; k0 < KDIM; k0 += BK) {
        float4 av4 = make_float4(0.f, 0.f, 0.f, 0.f);
        const int m = m0 + lr;
        if (m < M)
            av4 = *(const float4*)(A + (size_t)m * KDIM + k0 + lq * 4);
        const float4 bv4 = *(const float4*)(Wm + (size_t)(o0 + lr) * KDIM + k0 + lq * 4);

        As[lq*4+0][lr] = av4.x; As[lq*4+1][lr] = av4.y;
        As[lq*4+2][lr] = av4.z; As[lq*4+3][lr] = av4.w;
        Bs[lq*4+0][lr] = bv4.x; Bs[lq*4+1][lr] = bv4.y;
        Bs[lq*4+2][lr] = bv4.z; Bs[lq*4+3][lr] = bv4.w;
        __syncthreads();

#pragma unroll
        for (int kk = 0; kk < BK; kk++) {
            const float4 a4 = *(const float4*)&As[kk][ty * 4];
            const ull b01 = *(const ull*)&Bs[kk][tx * 4];
            const ull b23 = *(const ull*)&Bs[kk][tx * 4 + 2];
            ull a0 = dup2(a4.x), a1 = dup2(a4.y), a2 = dup2(a4.z), a3 = dup2(a4.w);
            fma2(acc[0][0], a0, b01); fma2(acc[0][1], a0, b23);
            fma2(acc[1][0], a1, b01); fma2(acc[1][1], a1, b23);
            fma2(acc[2][0], a2, b01); fma2(acc[2][1], a2, b23);
            fma2(acc[3][0], a3, b01); fma2(acc[3][1], a3, b23);
        }
        __syncthreads();
    }

#pragma unroll
    for (int i = 0; i < 4; i++) {
        const int m = m0 + ty * 4 + i;
        if (m < M) {
            float2 c01 = unpack2(acc[i][0]);
            float2 c23 = unpack2(acc[i][1]);
            float4 o = make_float4(c01.x, c01.y, c23.x, c23.y);
            *(float4*)(g_feat_src + (size_t)m * HD + o0 + tx * 4) = o;
        }
    }
}

// ---------------- K1b: el[n,h] = <feat_src[n,h,:], attn_l[h,:]>, er likewise -
__global__ __launch_bounds__(256) void score_kernel(
    const float* __restrict__ attn_l, const float* __restrict__ attn_r, int M)
{
    const int g = blockIdx.x * blockDim.x + threadIdx.x;
    const int node = g >> 5;
    const int lane = g & 31;
    if (node >= M) return;
    const float* row = g_feat_src + (size_t)node * HD;
#pragma unroll
    for (int h = 0; h < NHEAD; h++) {
        const int c0 = h * 64 + lane, c1 = c0 + 32;
        const float r0 = row[c0], r1 = row[c1];
        float pl = r0 * attn_l[c0] + r1 * attn_l[c1];
        float pr = r0 * attn_r[c0] + r1 * attn_r[c1];
#pragma unroll
        for (int off = 16; off > 0; off >>= 1) {
            pl += __shfl_down_sync(0xffffffffu, pl, off);
            pr += __shfl_down_sync(0xffffffffu, pr, off);
        }
        if (lane == 0) {
            g_el[(size_t)node * NHEAD + h] = pl;
            g_er[(size_t)node * NHEAD + h] = pr;
        }
    }
}

// ---------------- K2: per-dst edge softmax + weighted SpMM ------------------
// One CTA per destination node. 256 threads = one output column each
// (col = h*64 + d). Online (chunked) softmax so arbitrary degree is correct;
// dataset has uniform degree 16 -> exactly one chunk, unrolled gather.
#define CHUNK 16

__global__ __launch_bounds__(256) void agg_kernel(
    const int* __restrict__ row_ptr, const int* __restrict__ col_ind,
    float* __restrict__ out, int M)
{
    __shared__ int   s_src[CHUNK];
    __shared__ float s_e[CHUNK * NHEAD];
    __shared__ float s_w[CHUNK * NHEAD];
    __shared__ float s_m[NHEAD], s_sum[NHEAD], s_scale[NHEAD];

    const int n = blockIdx.x;
    if (n >= M) return;
    const int tid = threadIdx.x;
    const int h = tid >> 6;
    const int beg = row_ptr[n], end = row_ptr[n + 1];

    if (tid < NHEAD) { s_m[tid] = -INFINITY; s_sum[tid] = 0.f; }
    float acc = 0.f;
    __syncthreads();

    for (int base = beg; base < end; base += CHUNK) {
        const int cnt = min(CHUNK, end - base);
        if (tid < cnt) s_src[tid] = col_ind[base + tid];
        __syncthreads();

        if (tid < cnt * NHEAD) {
            const int j = tid >> 2, hh = tid & 3;
            float e = g_er[(size_t)s_src[j] * NHEAD + hh] +
                      g_el[(size_t)n * NHEAD + hh];
            e = (e > 0.f) ? e : 0.2f * e;
            s_e[j * NHEAD + hh] = e;
        }
        __syncthreads();

        if (tid < NHEAD) {
            float m = s_m[tid];
            for (int j = 0; j < cnt; j++) m = fmaxf(m, s_e[j * NHEAD + tid]);
            const float scale = expf(s_m[tid] - m);
            float sum = s_sum[tid] * scale;
            for (int j = 0; j < cnt; j++) {
                const float w = expf(s_e[j * NHEAD + tid] - m);
                s_w[j * NHEAD + tid] = w;
                sum += w;
            }
            s_m[tid] = m; s_sum[tid] = sum; s_scale[tid] = scale;
        }
        __syncthreads();

        acc *= s_scale[h];
        if (cnt == CHUNK) {
#pragma unroll
            for (int j = 0; j < CHUNK; j++)
                acc = fmaf(s_w[j * NHEAD + h],
                           g_feat_src[(size_t)s_src[j] * HD + tid], acc);
        } else {
            for (int j = 0; j < cnt; j++)
                acc = fmaf(s_w[j * NHEAD + h],
                           g_feat_src[(size_t)s_src[j] * HD + tid], acc);
        }
        __syncthreads();
    }

    out[(size_t)n * HD + tid] = (end > beg) ? acc / s_sum[h] : 0.f;
}

// ---------------- launch ----------------------------------------------------
extern "C" void kernel_launch(void* const* d_in, const int* in_sizes, int n_in,
                              void* d_out, int out_size)
{
    const int*   row_ptr = (const int*)d_in[0];
    const int*   col_ind = (const int*)d_in[1];
    const float* feat    = (const float*)d_in[2];
    const float* Wm      = (const float*)d_in[3];
    const float* attn_l  = (const float*)d_in[4];
    const float* attn_r  = (const float*)d_in[5];
    float* out = (float*)d_out;

    const int M = in_sizes[0] - 1;   // number of nodes

    dim3 ggrid((M + BM - 1) / BM, HD / BN);
    gemm_kernel<<<ggrid, 256>>>(feat, Wm, M);

    const int score_blocks = (M * 32 + 255) / 256;
    score_kernel<<<score_blocks, 256>>>(attn_l, attn_r, M);

    agg_kernel<<<M, 256>>>(row_ptr, col_ind, out, M);
}

// round 2
// speedup vs baseline: 1.5951x; 1.5951x over previous
#include <cuda_runtime.h>
#include <math.h>

// N=100000 nodes, IN=256, H=4, D=64, H*D=256
#define N_MAX 100000
#define KDIM 256
#define HD   256
#define NHEAD 4

typedef unsigned long long ull;

// ---------------- scratch (device globals) ---------------------------------
__device__ float g_feat_src[(size_t)N_MAX * HD];   // 102.4 MB
__device__ float g_el[(size_t)N_MAX * NHEAD];
__device__ float g_er[(size_t)N_MAX * NHEAD];

// ---------------- packed f32x2 helpers --------------------------------------
__device__ __forceinline__ ull dup2(float x) {
    ull r; asm("mov.b64 %0, {%1, %1};" : "=l"(r) : "f"(x)); return r;
}
__device__ __forceinline__ void fma2(ull& d, ull a, ull b) {
    asm("fma.rn.f32x2 %0, %1, %2, %0;" : "+l"(d) : "l"(a), "l"(b));
}
__device__ __forceinline__ float2 unpack2(ull v) {
    float2 r; asm("mov.b64 {%0, %1}, %2;" : "=f"(r.x), "=f"(r.y) : "l"(v)); return r;
}

// ---------------- K1: feat_src = feat @ W^T + fused el/er --------------------
// 128x128 tile, 256 threads, 8x8 per thread (cols split as tx*4 and 64+tx*4).
#define BM 128
#define BN 128
#define BK 16
#define LDS_ 132

__global__ __launch_bounds__(256, 2) void gemm_kernel(
    const float* __restrict__ A, const float* __restrict__ Wm,
    const float* __restrict__ attn_l, const float* __restrict__ attn_r, int M)
{
    __shared__ __align__(16) float As[BK][LDS_];
    __shared__ __align__(16) float Bs[BK][LDS_];

    const int tid = threadIdx.x;
    const int m0 = blockIdx.x * BM;
    const int o0 = blockIdx.y * BN;
    const int ty = tid >> 4;       // 0..15 row group (8 rows each)
    const int tx = tid & 15;       // 0..15 col group
    const int lr = tid >> 1;       // 0..127 load row
    const int kq = (tid & 1) * 8;  // which 8-float half of K per tile

    ull acc[8][4];
#pragma unroll
    for (int i = 0; i < 8; i++)
#pragma unroll
        for (int j = 0; j < 4; j++) acc[i][j] = 0ull;

    float4 pa0, pa1, pb0, pb1;
    const float4 fz = make_float4(0.f, 0.f, 0.f, 0.f);

    // prefetch tile 0
    {
        const int m = m0 + lr;
        if (m < M) {
            pa0 = *(const float4*)(A + (size_t)m * KDIM + kq);
            pa1 = *(const float4*)(A + (size_t)m * KDIM + kq + 4);
        } else { pa0 = fz; pa1 = fz; }
        pb0 = *(const float4*)(Wm + (size_t)(o0 + lr) * KDIM + kq);
        pb1 = *(const float4*)(Wm + (size_t)(o0 + lr) * KDIM + kq + 4);
    }
    As[kq+0][lr]=pa0.x; As[kq+1][lr]=pa0.y; As[kq+2][lr]=pa0.z; As[kq+3][lr]=pa0.w;
    As[kq+4][lr]=pa1.x; As[kq+5][lr]=pa1.y; As[kq+6][lr]=pa1.z; As[kq+7][lr]=pa1.w;
    Bs[kq+0][lr]=pb0.x; Bs[kq+1][lr]=pb0.y; Bs[kq+2][lr]=pb0.z; Bs[kq+3][lr]=pb0.w;
    Bs[kq+4][lr]=pb1.x; Bs[kq+5][lr]=pb1.y; Bs[kq+6][lr]=pb1.z; Bs[kq+7][lr]=pb1.w;
    __syncthreads();

    const int NT = KDIM / BK;
    for (int t = 0; t < NT; t++) {
        if (t + 1 < NT) {
            const int k0 = (t + 1) * BK + kq;
            const int m = m0 + lr;
            if (m < M) {
                pa0 = *(const float4*)(A + (size_t)m * KDIM + k0);
                pa1 = *(const float4*)(A + (size_t)m * KDIM + k0 + 4);
            } else { pa0 = fz; pa1 = fz; }
            pb0 = *(const float4*)(Wm + (size_t)(o0 + lr) * KDIM + k0);
            pb1 = *(const float4*)(Wm + (size_t)(o0 + lr) * KDIM + k0 + 4);
        }
#pragma unroll
        for (int kk = 0; kk < BK; kk++) {
            const float4 a0 = *(const float4*)&As[kk][ty * 8];
            const float4 a1 = *(const float4*)&As[kk][ty * 8 + 4];
            const ull* bp = (const ull*)&Bs[kk][tx * 4];
            const ull bl0 = bp[0], bl1 = bp[1];
            const ull* bq = (const ull*)&Bs[kk][64 + tx * 4];
            const ull bh0 = bq[0], bh1 = bq[1];
            ull ar;
            ar = dup2(a0.x); fma2(acc[0][0],ar,bl0); fma2(acc[0][1],ar,bl1); fma2(acc[0][2],ar,bh0); fma2(acc[0][3],ar,bh1);
            ar = dup2(a0.y); fma2(acc[1][0],ar,bl0); fma2(acc[1][1],ar,bl1); fma2(acc[1][2],ar,bh0); fma2(acc[1][3],ar,bh1);
            ar = dup2(a0.z); fma2(acc[2][0],ar,bl0); fma2(acc[2][1],ar,bl1); fma2(acc[2][2],ar,bh0); fma2(acc[2][3],ar,bh1);
            ar = dup2(a0.w); fma2(acc[3][0],ar,bl0); fma2(acc[3][1],ar,bl1); fma2(acc[3][2],ar,bh0); fma2(acc[3][3],ar,bh1);
            ar = dup2(a1.x); fma2(acc[4][0],ar,bl0); fma2(acc[4][1],ar,bl1); fma2(acc[4][2],ar,bh0); fma2(acc[4][3],ar,bh1);
            ar = dup2(a1.y); fma2(acc[5][0],ar,bl0); fma2(acc[5][1],ar,bl1); fma2(acc[5][2],ar,bh0); fma2(acc[5][3],ar,bh1);
            ar = dup2(a1.z); fma2(acc[6][0],ar,bl0); fma2(acc[6][1],ar,bl1); fma2(acc[6][2],ar,bh0); fma2(acc[6][3],ar,bh1);
            ar = dup2(a1.w); fma2(acc[7][0],ar,bl0); fma2(acc[7][1],ar,bl1); fma2(acc[7][2],ar,bh0); fma2(acc[7][3],ar,bh1);
        }
        __syncthreads();
        if (t + 1 < NT) {
            As[kq+0][lr]=pa0.x; As[kq+1][lr]=pa0.y; As[kq+2][lr]=pa0.z; As[kq+3][lr]=pa0.w;
            As[kq+4][lr]=pa1.x; As[kq+5][lr]=pa1.y; As[kq+6][lr]=pa1.z; As[kq+7][lr]=pa1.w;
            Bs[kq+0][lr]=pb0.x; Bs[kq+1][lr]=pb0.y; Bs[kq+2][lr]=pb0.z; Bs[kq+3][lr]=pb0.w;
            Bs[kq+4][lr]=pb1.x; Bs[kq+5][lr]=pb1.y; Bs[kq+6][lr]=pb1.z; Bs[kq+7][lr]=pb1.w;
            __syncthreads();
        }
    }

    // epilogue: store feat_src + fused el/er (each head's 64 cols are inside this tile)
    const float4 al0 = *(const float4*)(attn_l + o0 + tx * 4);
    const float4 al1 = *(const float4*)(attn_l + o0 + 64 + tx * 4);
    const float4 ar0 = *(const float4*)(attn_r + o0 + tx * 4);
    const float4 ar1 = *(const float4*)(attn_r + o0 + 64 + tx * 4);
    const int hbase = blockIdx.y * 2;

#pragma unroll
    for (int r = 0; r < 8; r++) {
        const int m = m0 + ty * 8 + r;
        const float2 c0 = unpack2(acc[r][0]);
        const float2 c1 = unpack2(acc[r][1]);
        const float2 c2 = unpack2(acc[r][2]);
        const float2 c3 = unpack2(acc[r][3]);
        float pl0 = c0.x*al0.x + c0.y*al0.y + c1.x*al0.z + c1.y*al0.w;
        float pl1 = c2.x*al1.x + c2.y*al1.y + c3.x*al1.z + c3.y*al1.w;
        float pr0 = c0.x*ar0.x + c0.y*ar0.y + c1.x*ar0.z + c1.y*ar0.w;
        float pr1 = c2.x*ar1.x + c2.y*ar1.y + c3.x*ar1.z + c3.y*ar1.w;
#pragma unroll
        for (int off = 1; off < 16; off <<= 1) {
            pl0 += __shfl_xor_sync(0xffffffffu, pl0, off);
            pl1 += __shfl_xor_sync(0xffffffffu, pl1, off);
            pr0 += __shfl_xor_sync(0xffffffffu, pr0, off);
            pr1 += __shfl_xor_sync(0xffffffffu, pr1, off);
        }
        if (m < M) {
            *(float4*)(g_feat_src + (size_t)m * HD + o0 + tx * 4)      = make_float4(c0.x, c0.y, c1.x, c1.y);
            *(float4*)(g_feat_src + (size_t)m * HD + o0 + 64 + tx * 4) = make_float4(c2.x, c2.y, c3.x, c3.y);
            if (tx == 0) {
                g_el[(size_t)m * NHEAD + hbase]     = pl0;
                g_el[(size_t)m * NHEAD + hbase + 1] = pl1;
                g_er[(size_t)m * NHEAD + hbase]     = pr0;
                g_er[(size_t)m * NHEAD + hbase + 1] = pr1;
            }
        }
    }
}

// ---------------- K2: warp-per-node edge softmax + SpMM ----------------------
__device__ __forceinline__ float4 f4max(float4 a, float4 b) {
    return make_float4(fmaxf(a.x,b.x), fmaxf(a.y,b.y), fmaxf(a.z,b.z), fmaxf(a.w,b.w));
}
__device__ __forceinline__ float4 f4shfl_xor(float4 v, int off) {
    float4 r;
    r.x = __shfl_xor_sync(0xffffffffu, v.x, off);
    r.y = __shfl_xor_sync(0xffffffffu, v.y, off);
    r.z = __shfl_xor_sync(0xffffffffu, v.z, off);
    r.w = __shfl_xor_sync(0xffffffffu, v.w, off);
    return r;
}
__device__ __forceinline__ float4 f4exp(float4 v) {
    return make_float4(__expf(v.x), __expf(v.y), __expf(v.z), __expf(v.w));
}
__device__ __forceinline__ float4 f4fma(float s, float4 v, float4 a) {
    a.x = fmaf(s, v.x, a.x); a.y = fmaf(s, v.y, a.y);
    a.z = fmaf(s, v.z, a.z); a.w = fmaf(s, v.w, a.w);
    return a;
}
__device__ __forceinline__ float f4sel(float4 v, int h) {
    return (h == 0) ? v.x : (h == 1) ? v.y : (h == 2) ? v.z : v.w;
}

__global__ __launch_bounds__(256) void agg_kernel(
    const int* __restrict__ row_ptr, const int* __restrict__ col_ind,
    float* __restrict__ out, int M)
{
    __shared__ __align__(16) float4 s_w[8][32];   // [warp][edge] = per-head weights

    const int wid  = threadIdx.x >> 5;
    const int lane = threadIdx.x & 31;
    const int n = blockIdx.x * 8 + wid;
    if (n >= M) return;

    const int beg = row_ptr[n];
    const int deg = row_ptr[n + 1] - beg;
    const float4 el4 = *(const float4*)(g_el + (size_t)n * NHEAD);
    const int h = lane >> 3;                       // head of this lane's 8 cols

    float4 acc_a = make_float4(0.f,0.f,0.f,0.f);
    float4 acc_b = make_float4(0.f,0.f,0.f,0.f);
    float4 m4 = make_float4(-INFINITY,-INFINITY,-INFINITY,-INFINITY);
    float4 s4 = make_float4(0.f,0.f,0.f,0.f);

    for (int base = 0; base < deg; base += 32) {
        const int cnt = min(32, deg - base);
        int src = 0;
        float4 e4 = make_float4(-INFINITY,-INFINITY,-INFINITY,-INFINITY);
        if (lane < cnt) {
            src = col_ind[beg + base + lane];
            const float4 er4 = *(const float4*)(g_er + (size_t)src * NHEAD);
            float ex = er4.x + el4.x, ey = er4.y + el4.y;
            float ez = er4.z + el4.z, ew = er4.w + el4.w;
            e4.x = (ex > 0.f) ? ex : 0.2f * ex;
            e4.y = (ey > 0.f) ? ey : 0.2f * ey;
            e4.z = (ez > 0.f) ? ez : 0.2f * ez;
            e4.w = (ew > 0.f) ? ew : 0.2f * ew;
        }
        // chunk max over warp
        float4 cm = e4;
#pragma unroll
        for (int off = 16; off > 0; off >>= 1) cm = f4max(cm, f4shfl_xor(cm, off));
        const float4 nm = f4max(m4, cm);
        const float4 scale = f4exp(make_float4(m4.x-nm.x, m4.y-nm.y, m4.z-nm.z, m4.w-nm.w));
        m4 = nm;
        float4 w4 = f4exp(make_float4(e4.x-nm.x, e4.y-nm.y, e4.z-nm.z, e4.w-nm.w));
        // inactive lanes: e4=-inf -> w=0 automatically
        float4 cs = w4;
#pragma unroll
        for (int off = 16; off > 0; off >>= 1) {
            const float4 o = f4shfl_xor(cs, off);
            cs.x += o.x; cs.y += o.y; cs.z += o.z; cs.w += o.w;
        }
        s4.x = s4.x * scale.x + cs.x; s4.y = s4.y * scale.y + cs.y;
        s4.z = s4.z * scale.z + cs.z; s4.w = s4.w * scale.w + cs.w;

        const float sc_h = f4sel(scale, h);
        acc_a.x*=sc_h; acc_a.y*=sc_h; acc_a.z*=sc_h; acc_a.w*=sc_h;
        acc_b.x*=sc_h; acc_b.y*=sc_h; acc_b.z*=sc_h; acc_b.w*=sc_h;

        s_w[wid][lane] = w4;
        __syncwarp();

#pragma unroll 4
        for (int j = 0; j < cnt; j++) {
            const int srcj = __shfl_sync(0xffffffffu, src, j);
            const float w = ((const float*)&s_w[wid][j])[h];
            const float4* row = (const float4*)(g_feat_src + (size_t)srcj * HD) + lane * 2;
            acc_a = f4fma(w, row[0], acc_a);
            acc_b = f4fma(w, row[1], acc_b);
        }
        __syncwarp();
    }

    const float inv = (deg > 0) ? 1.0f / f4sel(s4, h) : 0.f;
    acc_a.x*=inv; acc_a.y*=inv; acc_a.z*=inv; acc_a.w*=inv;
    acc_b.x*=inv; acc_b.y*=inv; acc_b.z*=inv; acc_b.w*=inv;

    float4* o = (float4*)(out + (size_t)n * HD) + lane * 2;
    o[0] = acc_a;
    o[1] = acc_b;
}

// ---------------- launch -----------------------------------------------------
extern "C" void kernel_launch(void* const* d_in, const int* in_sizes, int n_in,
                              void* d_out, int out_size)
{
    const int*   row_ptr = (const int*)d_in[0];
    const int*   col_ind = (const int*)d_in[1];
    const float* feat    = (const float*)d_in[2];
    const float* Wm      = (const float*)d_in[3];
    const float* attn_l  = (const float*)d_in[4];
    const float* attn_r  = (const float*)d_in[5];
    float* out = (float*)d_out;

    const int M = in_sizes[0] - 1;

    dim3 ggrid((M + BM - 1) / BM, HD / BN);
    gemm_kernel<<<ggrid, 256>>>(feat, Wm, attn_l, attn_r, M);

    agg_kernel<<<(M + 7) / 8, 256>>>(row_ptr, col_ind, out, M);
}

// round 5
// speedup vs baseline: 2.1519x; 1.3491x over previous
#include <cuda_runtime.h>
#include <cuda_bf16.h>
#include <math.h>
#include <cstdint>

// N=100000 nodes, IN=256, H=4, D=64, H*D=256
#define N_MAX 100000
#define KDIM 256
#define HD   256
#define NHEAD 4

// ---------------- scratch (device globals) ---------------------------------
__device__ float g_feat_src[(size_t)N_MAX * HD];       // 102.4 MB
__device__ float g_el[(size_t)N_MAX * NHEAD];
__device__ float g_er[(size_t)N_MAX * NHEAD];
// W pre-arranged in mma.sync B-fragment layout:
// entry[(kstep*32 + nt)*32 + lane] = {bh0, bh1, bl0, bl1} (uint4, 16B)
// where b0 = {W[n][k0], W[n][k0+1]}, b1 = {W[n][k0+8], W[n][k0+9]},
// n = nt*8 + (lane>>2), k0 = kstep*16 + (lane&3)*2
__device__ uint4 g_Wfrag[16 * 32 * 32];                // 256 KB

// ---------------- helpers ----------------------------------------------------
__device__ __forceinline__ uint32_t smem_u32(const void* p) {
    uint32_t a;
    asm("{ .reg .u64 t; cvta.to.shared.u64 t, %1; cvt.u32.u64 %0, t; }"
        : "=r"(a) : "l"(p));
    return a;
}

#define MMA16816(d, a0, a1, a2, a3, b0, b1) \
    asm volatile("mma.sync.aligned.m16n8k16.row.col.f32.bf16.bf16.f32 " \
        "{%0,%1,%2,%3}, {%4,%5,%6,%7}, {%8,%9}, {%0,%1,%2,%3};" \
        : "+f"((d)[0]), "+f"((d)[1]), "+f"((d)[2]), "+f"((d)[3]) \
        : "r"(a0), "r"(a1), "r"(a2), "r"(a3), "r"(b0), "r"(b1))

#define CP_ASYNC16(s, g) \
    asm volatile("cp.async.cg.shared.global [%0], [%1], 16;" :: "r"(s), "l"(g))
#define CP_COMMIT() asm volatile("cp.async.commit_group;" ::: "memory")
#define CP_WAIT(n)  asm volatile("cp.async.wait_group %0;" :: "n"(n) : "memory")

__device__ __forceinline__ uint32_t pack_bf16x2(float lo, float hi) {
    __nv_bfloat162 v(__float2bfloat16(lo), __float2bfloat16(hi));  // .x = lo half
    return *reinterpret_cast<uint32_t*>(&v);
}

// ---------------- K0: W -> fragment-layout bf16 hi/lo ------------------------
__global__ __launch_bounds__(256) void prep_w_kernel(const float* __restrict__ W) {
    const int idx = blockIdx.x * 256 + threadIdx.x;    // 0..16383
    const int kstep = idx >> 10;
    const int nt    = (idx >> 5) & 31;
    const int lane  = idx & 31;
    const int n  = nt * 8 + (lane >> 2);
    const int k0 = kstep * 16 + (lane & 3) * 2;
    const float2 vA = *(const float2*)(W + (size_t)n * KDIM + k0);
    const float2 vB = *(const float2*)(W + (size_t)n * KDIM + k0 + 8);

    float hA0 = __bfloat162float(__float2bfloat16(vA.x));
    float hA1 = __bfloat162float(__float2bfloat16(vA.y));
    float hB0 = __bfloat162float(__float2bfloat16(vB.x));
    float hB1 = __bfloat162float(__float2bfloat16(vB.y));

    uint4 e;
    e.x = pack_bf16x2(hA0, hA1);                       // bh0
    e.y = pack_bf16x2(hB0, hB1);                       // bh1
    e.z = pack_bf16x2(vA.x - hA0, vA.y - hA1);         // bl0
    e.w = pack_bf16x2(vB.x - hB0, vB.y - hB1);         // bl1
    g_Wfrag[idx] = e;
}

// ---------------- K1: mma.sync GEMM + fused el/er ----------------------------
// CTA: 128 M-rows x full N=256, K=256. 512 threads = 16 warps (4M x 4N),
// warp tile 32x64. A staged full-K in smem (frag layout, hi/lo).
// B double-buffered per 2-kstep chunk via cp.async.
#define SMEM_AH 0
#define SMEM_AL 65536
#define SMEM_B0 131072
#define SMEM_B1 163840
#define SMEM_TOT 196608

__global__ void __launch_bounds__(512, 1) gemm_mma_kernel(
    const float* __restrict__ A,
    const float* __restrict__ attn_l, const float* __restrict__ attn_r, int M)
{
    extern __shared__ char smem[];
    const uint32_t sb = smem_u32(smem);
    const int tid  = threadIdx.x;
    const int lane = tid & 31;
    const int wid  = tid >> 5;
    const int warp_m = wid & 3;        // 4 M-groups of 32 rows
    const int warp_n = wid >> 2;       // 4 N-groups of 64 cols (= one head each)
    const int m0 = blockIdx.x * 128;

    // ---- prefetch B chunks 0 and 1 (each 2 ksteps = 2048 entries = 32KB) ----
    {
        const uint4* src = g_Wfrag;
#pragma unroll
        for (int p = 0; p < 4; p++) {
            const int e = p * 512 + tid;
            CP_ASYNC16(sb + SMEM_B0 + e * 16, (const void*)(src + e));
        }
        CP_COMMIT();
#pragma unroll
        for (int p = 0; p < 4; p++) {
            const int e = p * 512 + tid;
            CP_ASYNC16(sb + SMEM_B1 + e * 16, (const void*)(src + 2048 + e));
        }
        CP_COMMIT();
    }

    // ---- stage A: 128 rows x 256 fp32 -> bf16 hi/lo in frag layout ----------
    // A-fragment for m16n8k16: thread lane holds a0={A[r][k0],A[r][k0+1]},
    // a1={A[r+8][k0],A[r+8][k0+1]}, a2={A[r][k0+8],...}, a3={A[r+8][k0+8],...}
    // with r = lane>>2, k0 = (lane&3)*2, per 16x16 tile. We store tiles as
    // [mtile(8)][kstep(16)][lane(32)][16B], 16B = {a0,a1,a2,a3}.
    {
        const int rsub = tid >> 7;            // 0..3
        const int kp   = tid & 127;           // float2 index along K
#pragma unroll
        for (int i = 0; i < 32; i++) {
            const int r = i * 4 + rsub;       // 0..127
            const int m = m0 + r;
            float2 v = make_float2(0.f, 0.f);
            if (m < M) v = *(const float2*)(A + (size_t)m * KDIM + kp * 2);
            const float h0 = __bfloat162float(__float2bfloat16(v.x));
            const float h1 = __bfloat162float(__float2bfloat16(v.y));
            const uint32_t hp = pack_bf16x2(h0, h1);
            const uint32_t lp = pack_bf16x2(v.x - h0, v.y - h1);

            const int r16 = r & 15;
            const int k = kp * 2;
            const int kstep = k >> 4, kin = k & 15;
            const int quad   = (r16 >> 3) + 2 * (kin >> 3);         // which a-reg
            const int lane_s = (r16 & 7) * 4 + ((kin & 7) >> 1);    // owning lane
            const uint32_t off = (uint32_t)((((r >> 4) * 16 + kstep) * 32 + lane_s) * 16 + quad * 4);
            *(uint32_t*)(smem + SMEM_AH + off) = hp;
            *(uint32_t*)(smem + SMEM_AL + off) = lp;
        }
    }
    __syncthreads();

    float acc[2][8][4];
#pragma unroll
    for (int mt = 0; mt < 2; mt++)
#pragma unroll
        for (int nt = 0; nt < 8; nt++)
#pragma unroll
            for (int q = 0; q < 4; q++) acc[mt][nt][q] = 0.f;

    // ---- main loop: 8 chunks of 2 ksteps ------------------------------------
    for (int c = 0; c < 8; c++) {
        if (c == 7) { CP_WAIT(0); } else { CP_WAIT(1); }
        __syncthreads();
        const uint32_t bchunk = (c & 1) ? SMEM_B1 : SMEM_B0;

#pragma unroll
        for (int ksi = 0; ksi < 2; ksi++) {
            const int ks = c * 2 + ksi;
            const uint32_t a0off = (uint32_t)((((warp_m * 2 + 0) * 16 + ks) * 32 + lane) * 16);
            const uint32_t a1off = (uint32_t)((((warp_m * 2 + 1) * 16 + ks) * 32 + lane) * 16);
            const uint4 Ah0 = *(const uint4*)(smem + SMEM_AH + a0off);
            const uint4 Ah1 = *(const uint4*)(smem + SMEM_AH + a1off);
            const uint4 Al0 = *(const uint4*)(smem + SMEM_AL + a0off);
            const uint4 Al1 = *(const uint4*)(smem + SMEM_AL + a1off);
#pragma unroll
            for (int nt = 0; nt < 8; nt++) {
                const uint32_t boff = (uint32_t)(((ksi * 32 + warp_n * 8 + nt) * 32 + lane) * 16);
                const uint4 B = *(const uint4*)(smem + bchunk + boff);
                MMA16816(acc[0][nt], Ah0.x, Ah0.y, Ah0.z, Ah0.w, B.x, B.y);
                MMA16816(acc[0][nt], Al0.x, Al0.y, Al0.z, Al0.w, B.x, B.y);
                MMA16816(acc[0][nt], Ah0.x, Ah0.y, Ah0.z, Ah0.w, B.z, B.w);
                MMA16816(acc[1][nt], Ah1.x, Ah1.y, Ah1.z, Ah1.w, B.x, B.y);
                MMA16816(acc[1][nt], Al1.x, Al1.y, Al1.z, Al1.w, B.x, B.y);
                MMA16816(acc[1][nt], Ah1.x, Ah1.y, Ah1.z, Ah1.w, B.z, B.w);
            }
        }
        __syncthreads();
        if (c + 2 < 8) {
            const uint4* src = g_Wfrag + (c + 2) * 2048;
            const uint32_t dst = sb + ((c & 1) ? SMEM_B1 : SMEM_B0);
#pragma unroll
            for (int p = 0; p < 4; p++) {
                const int e = p * 512 + tid;
                CP_ASYNC16(dst + e * 16, (const void*)(src + e));
            }
            CP_COMMIT();
        }
    }

    // ---- epilogue: store feat_src + fused el/er ------------------------------
    // acc[mt][nt]: d0,d1 -> row rbase+mt*16, cols c0,c0+1 ; d2,d3 -> row +8
    const int head = warp_n;
    float pl[2][2] = {{0.f, 0.f}, {0.f, 0.f}};
    float pr[2][2] = {{0.f, 0.f}, {0.f, 0.f}};
    const int rbase = m0 + warp_m * 32 + (lane >> 2);

#pragma unroll
    for (int mt = 0; mt < 2; mt++) {
        const int row0 = rbase + mt * 16;
        const int row1 = row0 + 8;
#pragma unroll
        for (int nt = 0; nt < 8; nt++) {
            const int c0 = warp_n * 64 + nt * 8 + (lane & 3) * 2;
            const float d0 = acc[mt][nt][0], d1 = acc[mt][nt][1];
            const float d2 = acc[mt][nt][2], d3 = acc[mt][nt][3];
            const float al0 = __ldg(attn_l + c0), al1 = __ldg(attn_l + c0 + 1);
            const float ar0 = __ldg(attn_r + c0), ar1 = __ldg(attn_r + c0 + 1);
            pl[mt][0] = fmaf(d0, al0, fmaf(d1, al1, pl[mt][0]));
            pl[mt][1] = fmaf(d2, al0, fmaf(d3, al1, pl[mt][1]));
            pr[mt][0] = fmaf(d0, ar0, fmaf(d1, ar1, pr[mt][0]));
            pr[mt][1] = fmaf(d2, ar0, fmaf(d3, ar1, pr[mt][1]));
            if (row0 < M)
                *(float2*)(g_feat_src + (size_t)row0 * HD + c0) = make_float2(d0, d1);
            if (row1 < M)
                *(float2*)(g_feat_src + (size_t)row1 * HD + c0) = make_float2(d2, d3);
        }
    }
    // reduce over the 4 lanes sharing a row (lane&3 varies col)
#pragma unroll
    for (int mt = 0; mt < 2; mt++)
#pragma unroll
        for (int rh = 0; rh < 2; rh++) {
#pragma unroll
            for (int off = 1; off < 4; off <<= 1) {
                pl[mt][rh] += __shfl_xor_sync(0xffffffffu, pl[mt][rh], off);
                pr[mt][rh] += __shfl_xor_sync(0xffffffffu, pr[mt][rh], off);
            }
        }
    if ((lane & 3) == 0) {
#pragma unroll
        for (int mt = 0; mt < 2; mt++)
#pragma unroll
            for (int rh = 0; rh < 2; rh++) {
                const int row = rbase + mt * 16 + rh * 8;
                if (row < M) {
                    g_el[(size_t)row * NHEAD + head] = pl[mt][rh];
                    g_er[(size_t)row * NHEAD + head] = pr[mt][rh];
                }
            }
    }
}

// ---------------- K2: warp-per-node edge softmax + SpMM ----------------------
__device__ __forceinline__ float4 f4max(float4 a, float4 b) {
    return make_float4(fmaxf(a.x,b.x), fmaxf(a.y,b.y), fmaxf(a.z,b.z), fmaxf(a.w,b.w));
}
__device__ __forceinline__ float4 f4shfl_xor(float4 v, int off) {
    float4 r;
    r.x = __shfl_xor_sync(0xffffffffu, v.x, off);
    r.y = __shfl_xor_sync(0xffffffffu, v.y, off);
    r.z = __shfl_xor_sync(0xffffffffu, v.z, off);
    r.w = __shfl_xor_sync(0xffffffffu, v.w, off);
    return r;
}
__device__ __forceinline__ float4 f4exp(float4 v) {
    return make_float4(__expf(v.x), __expf(v.y), __expf(v.z), __expf(v.w));
}
__device__ __forceinline__ float4 f4fma(float s, float4 v, float4 a) {
    a.x = fmaf(s, v.x, a.x); a.y = fmaf(s, v.y, a.y);
    a.z = fmaf(s, v.z, a.z); a.w = fmaf(s, v.w, a.w);
    return a;
}
__device__ __forceinline__ float f4sel(float4 v, int h) {
    return (h == 0) ? v.x : (h == 1) ? v.y : (h == 2) ? v.z : v.w;
}

__global__ __launch_bounds__(256) void agg_kernel(
    const int* __restrict__ row_ptr, const int* __restrict__ col_ind,
    float* __restrict__ out, int M)
{
    __shared__ __align__(16) float4 s_w[8][32];

    const int wid  = threadIdx.x >> 5;
    const int lane = threadIdx.x & 31;
    const int n = blockIdx.x * 8 + wid;
    if (n >= M) return;

    const int beg = row_ptr[n];
    const int deg = row_ptr[n + 1] - beg;
    const float4 el4 = *(const float4*)(g_el + (size_t)n * NHEAD);
    const int h = lane >> 3;

    float4 acc_a = make_float4(0.f,0.f,0.f,0.f);
    float4 acc_b = make_float4(0.f,0.f,0.f,0.f);
    float4 m4 = make_float4(-INFINITY,-INFINITY,-INFINITY,-INFINITY);
    float4 s4 = make_float4(0.f,0.f,0.f,0.f);

    for (int base = 0; base < deg; base += 32) {
        const int cnt = min(32, deg - base);
        int src = 0;
        float4 e4 = make_float4(-INFINITY,-INFINITY,-INFINITY,-INFINITY);
        if (lane < cnt) {
            src = col_ind[beg + base + lane];
            const float4 er4 = *(const float4*)(g_er + (size_t)src * NHEAD);
            float ex = er4.x + el4.x, ey = er4.y + el4.y;
            float ez = er4.z + el4.z, ew = er4.w + el4.w;
            e4.x = (ex > 0.f) ? ex : 0.2f * ex;
            e4.y = (ey > 0.f) ? ey : 0.2f * ey;
            e4.z = (ez > 0.f) ? ez : 0.2f * ez;
            e4.w = (ew > 0.f) ? ew : 0.2f * ew;
        }
        float4 cm = e4;
#pragma unroll
        for (int off = 16; off > 0; off >>= 1) cm = f4max(cm, f4shfl_xor(cm, off));
        const float4 nm = f4max(m4, cm);
        const float4 scale = f4exp(make_float4(m4.x-nm.x, m4.y-nm.y, m4.z-nm.z, m4.w-nm.w));
        m4 = nm;
        float4 w4 = f4exp(make_float4(e4.x-nm.x, e4.y-nm.y, e4.z-nm.z, e4.w-nm.w));
        float4 cs = w4;
#pragma unroll
        for (int off = 16; off > 0; off >>= 1) {
            const float4 o = f4shfl_xor(cs, off);
            cs.x += o.x; cs.y += o.y; cs.z += o.z; cs.w += o.w;
        }
        s4.x = s4.x * scale.x + cs.x; s4.y = s4.y * scale.y + cs.y;
        s4.z = s4.z * scale.z + cs.z; s4.w = s4.w * scale.w + cs.w;

        const float sc_h = f4sel(scale, h);
        acc_a.x*=sc_h; acc_a.y*=sc_h; acc_a.z*=sc_h; acc_a.w*=sc_h;
        acc_b.x*=sc_h; acc_b.y*=sc_h; acc_b.z*=sc_h; acc_b.w*=sc_h;

        s_w[wid][lane] = w4;
        __syncwarp();

#pragma unroll 4
        for (int j = 0; j < cnt; j++) {
            const int srcj = __shfl_sync(0xffffffffu, src, j);
            const float w = ((const float*)&s_w[wid][j])[h];
            const float4* row = (const float4*)(g_feat_src + (size_t)srcj * HD) + lane * 2;
            acc_a = f4fma(w, row[0], acc_a);
            acc_b = f4fma(w, row[1], acc_b);
        }
        __syncwarp();
    }

    const float inv = (deg > 0) ? 1.0f / f4sel(s4, h) : 0.f;
    acc_a.x*=inv; acc_a.y*=inv; acc_a.z*=inv; acc_a.w*=inv;
    acc_b.x*=inv; acc_b.y*=inv; acc_b.z*=inv; acc_b.w*=inv;

    float4* o = (float4*)(out + (size_t)n * HD) + lane * 2;
    o[0] = acc_a;
    o[1] = acc_b;
}

// ---------------- launch -----------------------------------------------------
extern "C" void kernel_launch(void* const* d_in, const int* in_sizes, int n_in,
                              void* d_out, int out_size)
{
    const int*   row_ptr = (const int*)d_in[0];
    const int*   col_ind = (const int*)d_in[1];
    const float* feat    = (const float*)d_in[2];
    const float* Wm      = (const float*)d_in[3];
    const float* attn_l  = (const float*)d_in[4];
    const float* attn_r  = (const float*)d_in[5];
    float* out = (float*)d_out;

    const int M = in_sizes[0] - 1;

    cudaFuncSetAttribute(gemm_mma_kernel,
                         cudaFuncAttributeMaxDynamicSharedMemorySize, SMEM_TOT);

    prep_w_kernel<<<64, 256>>>(Wm);
    gemm_mma_kernel<<<(M + 127) / 128, 512, SMEM_TOT>>>(feat, attn_l, attn_r, M);
    agg_kernel<<<(M + 7) / 8, 256>>>(row_ptr, col_ind, out, M);
}

// round 6
// speedup vs baseline: 2.6035x; 1.2099x over previous
#include <cuda_runtime.h>
#include <cuda_bf16.h>
#include <cuda_fp16.h>
#include <math.h>
#include <cstdint>

// N=100000 nodes, IN=256, H=4, D=64, H*D=256
#define N_MAX 100000
#define KDIM 256
#define HD   256
#define NHEAD 4

// ---------------- scratch (device globals) ---------------------------------
__device__ __half g_feat_h[(size_t)N_MAX * HD];        // 51.2 MB (fp16)
__device__ float g_el[(size_t)N_MAX * NHEAD];
__device__ float g_er[(size_t)N_MAX * NHEAD];
// W pre-arranged in mma.sync B-fragment layout:
// entry[(kstep*32 + nt)*32 + lane] = {bh0, bh1, bl0, bl1} (uint4, 16B)
__device__ uint4 g_Wfrag[16 * 32 * 32];                // 256 KB

// ---------------- helpers ----------------------------------------------------
__device__ __forceinline__ uint32_t smem_u32(const void* p) {
    uint32_t a;
    asm("{ .reg .u64 t; cvta.to.shared.u64 t, %1; cvt.u32.u64 %0, t; }"
        : "=r"(a) : "l"(p));
    return a;
}

#define MMA16816(d, a0, a1, a2, a3, b0, b1) \
    asm volatile("mma.sync.aligned.m16n8k16.row.col.f32.bf16.bf16.f32 " \
        "{%0,%1,%2,%3}, {%4,%5,%6,%7}, {%8,%9}, {%0,%1,%2,%3};" \
        : "+f"((d)[0]), "+f"((d)[1]), "+f"((d)[2]), "+f"((d)[3]) \
        : "r"(a0), "r"(a1), "r"(a2), "r"(a3), "r"(b0), "r"(b1))

#define CP_ASYNC16(s, g) \
    asm volatile("cp.async.cg.shared.global [%0], [%1], 16;" :: "r"(s), "l"(g))
#define CP_COMMIT() asm volatile("cp.async.commit_group;" ::: "memory")
#define CP_WAIT(n)  asm volatile("cp.async.wait_group %0;" :: "n"(n) : "memory")

__device__ __forceinline__ uint32_t pack_bf16x2(float lo, float hi) {
    __nv_bfloat162 v(__float2bfloat16(lo), __float2bfloat16(hi));
    return *reinterpret_cast<uint32_t*>(&v);
}

// ---------------- K0: W -> fragment-layout bf16 hi/lo ------------------------
__global__ __launch_bounds__(256) void prep_w_kernel(const float* __restrict__ W) {
    const int idx = blockIdx.x * 256 + threadIdx.x;    // 0..16383
    const int kstep = idx >> 10;
    const int nt    = (idx >> 5) & 31;
    const int lane  = idx & 31;
    const int n  = nt * 8 + (lane >> 2);
    const int k0 = kstep * 16 + (lane & 3) * 2;
    const float2 vA = *(const float2*)(W + (size_t)n * KDIM + k0);
    const float2 vB = *(const float2*)(W + (size_t)n * KDIM + k0 + 8);

    float hA0 = __bfloat162float(__float2bfloat16(vA.x));
    float hA1 = __bfloat162float(__float2bfloat16(vA.y));
    float hB0 = __bfloat162float(__float2bfloat16(vB.x));
    float hB1 = __bfloat162float(__float2bfloat16(vB.y));

    uint4 e;
    e.x = pack_bf16x2(hA0, hA1);
    e.y = pack_bf16x2(hB0, hB1);
    e.z = pack_bf16x2(vA.x - hA0, vA.y - hA1);
    e.w = pack_bf16x2(vB.x - hB0, vB.y - hB1);
    g_Wfrag[idx] = e;
}

// ---------------- K1: mma.sync GEMM + fused el/er ----------------------------
#define SMEM_AH 0
#define SMEM_AL 65536
#define SMEM_B0 131072
#define SMEM_B1 163840
#define SMEM_TOT 196608

__global__ void __launch_bounds__(512, 1) gemm_mma_kernel(
    const float* __restrict__ A,
    const float* __restrict__ attn_l, const float* __restrict__ attn_r, int M)
{
    extern __shared__ char smem[];
    const uint32_t sb = smem_u32(smem);
    const int tid  = threadIdx.x;
    const int lane = tid & 31;
    const int wid  = tid >> 5;
    const int warp_m = wid & 3;        // 4 M-groups of 32 rows
    const int warp_n = wid >> 2;       // 4 N-groups of 64 cols (one head each)
    const int m0 = blockIdx.x * 128;

    // ---- prefetch B chunks 0 and 1 ----
    {
        const uint4* src = g_Wfrag;
#pragma unroll
        for (int p = 0; p < 4; p++) {
            const int e = p * 512 + tid;
            CP_ASYNC16(sb + SMEM_B0 + e * 16, (const void*)(src + e));
        }
        CP_COMMIT();
#pragma unroll
        for (int p = 0; p < 4; p++) {
            const int e = p * 512 + tid;
            CP_ASYNC16(sb + SMEM_B1 + e * 16, (const void*)(src + 2048 + e));
        }
        CP_COMMIT();
    }

    // ---- stage A: 128 rows x 256 fp32 -> bf16 hi/lo in frag layout ----------
    // float4 loads: thread handles float4 index kq of row r.
    {
        const int rsub = tid >> 6;            // 0..7
        const int kq   = tid & 63;            // float4 index along K
        const int k    = kq * 4;
        const int kstep = k >> 4, kin = k & 15;
#pragma unroll
        for (int i = 0; i < 16; i++) {
            const int r = i * 8 + rsub;       // 0..127
            const int m = m0 + r;
            float4 v = make_float4(0.f, 0.f, 0.f, 0.f);
            if (m < M) v = *(const float4*)(A + (size_t)m * KDIM + k);
            const float h0 = __bfloat162float(__float2bfloat16(v.x));
            const float h1 = __bfloat162float(__float2bfloat16(v.y));
            const float h2 = __bfloat162float(__float2bfloat16(v.z));
            const float h3 = __bfloat162float(__float2bfloat16(v.w));
            const uint32_t hp0 = pack_bf16x2(h0, h1);
            const uint32_t hp1 = pack_bf16x2(h2, h3);
            const uint32_t lp0 = pack_bf16x2(v.x - h0, v.y - h1);
            const uint32_t lp1 = pack_bf16x2(v.z - h2, v.w - h3);

            const int r16 = r & 15;
            const int quad   = (r16 >> 3) + 2 * (kin >> 3);
            const int lane_s = (r16 & 7) * 4 + ((kin & 7) >> 1);
            const uint32_t off = (uint32_t)((((r >> 4) * 16 + kstep) * 32 + lane_s) * 16 + quad * 4);
            *(uint32_t*)(smem + SMEM_AH + off)      = hp0;
            *(uint32_t*)(smem + SMEM_AH + off + 16) = hp1;
            *(uint32_t*)(smem + SMEM_AL + off)      = lp0;
            *(uint32_t*)(smem + SMEM_AL + off + 16) = lp1;
        }
    }
    __syncthreads();

    float acc[2][8][4];
#pragma unroll
    for (int mt = 0; mt < 2; mt++)
#pragma unroll
        for (int nt = 0; nt < 8; nt++)
#pragma unroll
            for (int q = 0; q < 4; q++) acc[mt][nt][q] = 0.f;

    // ---- main loop: 8 chunks of 2 ksteps ------------------------------------
    for (int c = 0; c < 8; c++) {
        if (c == 7) { CP_WAIT(0); } else { CP_WAIT(1); }
        __syncthreads();
        const uint32_t bchunk = (c & 1) ? SMEM_B1 : SMEM_B0;

#pragma unroll
        for (int ksi = 0; ksi < 2; ksi++) {
            const int ks = c * 2 + ksi;
            const uint32_t a0off = (uint32_t)((((warp_m * 2 + 0) * 16 + ks) * 32 + lane) * 16);
            const uint32_t a1off = (uint32_t)((((warp_m * 2 + 1) * 16 + ks) * 32 + lane) * 16);
            const uint4 Ah0 = *(const uint4*)(smem + SMEM_AH + a0off);
            const uint4 Ah1 = *(const uint4*)(smem + SMEM_AH + a1off);
            const uint4 Al0 = *(const uint4*)(smem + SMEM_AL + a0off);
            const uint4 Al1 = *(const uint4*)(smem + SMEM_AL + a1off);
#pragma unroll
            for (int nt = 0; nt < 8; nt++) {
                const uint32_t boff = (uint32_t)(((ksi * 32 + warp_n * 8 + nt) * 32 + lane) * 16);
                const uint4 B = *(const uint4*)(smem + bchunk + boff);
                MMA16816(acc[0][nt], Ah0.x, Ah0.y, Ah0.z, Ah0.w, B.x, B.y);
                MMA16816(acc[0][nt], Al0.x, Al0.y, Al0.z, Al0.w, B.x, B.y);
                MMA16816(acc[0][nt], Ah0.x, Ah0.y, Ah0.z, Ah0.w, B.z, B.w);
                MMA16816(acc[1][nt], Ah1.x, Ah1.y, Ah1.z, Ah1.w, B.x, B.y);
                MMA16816(acc[1][nt], Al1.x, Al1.y, Al1.z, Al1.w, B.x, B.y);
                MMA16816(acc[1][nt], Ah1.x, Ah1.y, Ah1.z, Ah1.w, B.z, B.w);
            }
        }
        __syncthreads();
        if (c + 2 < 8) {
            const uint4* src = g_Wfrag + (c + 2) * 2048;
            const uint32_t dst = sb + ((c & 1) ? SMEM_B1 : SMEM_B0);
#pragma unroll
            for (int p = 0; p < 4; p++) {
                const int e = p * 512 + tid;
                CP_ASYNC16(dst + e * 16, (const void*)(src + e));
            }
            CP_COMMIT();
        }
    }

    // ---- epilogue: store feat_src (fp16) + fused el/er -----------------------
    const int head = warp_n;
    float pl[2][2] = {{0.f, 0.f}, {0.f, 0.f}};
    float pr[2][2] = {{0.f, 0.f}, {0.f, 0.f}};
    const int rbase = m0 + warp_m * 32 + (lane >> 2);

#pragma unroll
    for (int mt = 0; mt < 2; mt++) {
        const int row0 = rbase + mt * 16;
        const int row1 = row0 + 8;
#pragma unroll
        for (int nt = 0; nt < 8; nt++) {
            const int c0 = warp_n * 64 + nt * 8 + (lane & 3) * 2;
            const float d0 = acc[mt][nt][0], d1 = acc[mt][nt][1];
            const float d2 = acc[mt][nt][2], d3 = acc[mt][nt][3];
            const float al0 = __ldg(attn_l + c0), al1 = __ldg(attn_l + c0 + 1);
            const float ar0 = __ldg(attn_r + c0), ar1 = __ldg(attn_r + c0 + 1);
            pl[mt][0] = fmaf(d0, al0, fmaf(d1, al1, pl[mt][0]));
            pl[mt][1] = fmaf(d2, al0, fmaf(d3, al1, pl[mt][1]));
            pr[mt][0] = fmaf(d0, ar0, fmaf(d1, ar1, pr[mt][0]));
            pr[mt][1] = fmaf(d2, ar0, fmaf(d3, ar1, pr[mt][1]));
            if (row0 < M)
                *(__half2*)(g_feat_h + (size_t)row0 * HD + c0) =
                    __floats2half2_rn(d0, d1);
            if (row1 < M)
                *(__half2*)(g_feat_h + (size_t)row1 * HD + c0) =
                    __floats2half2_rn(d2, d3);
        }
    }
#pragma unroll
    for (int mt = 0; mt < 2; mt++)
#pragma unroll
        for (int rh = 0; rh < 2; rh++) {
#pragma unroll
            for (int off = 1; off < 4; off <<= 1) {
                pl[mt][rh] += __shfl_xor_sync(0xffffffffu, pl[mt][rh], off);
                pr[mt][rh] += __shfl_xor_sync(0xffffffffu, pr[mt][rh], off);
            }
        }
    if ((lane & 3) == 0) {
#pragma unroll
        for (int mt = 0; mt < 2; mt++)
#pragma unroll
            for (int rh = 0; rh < 2; rh++) {
                const int row = rbase + mt * 16 + rh * 8;
                if (row < M) {
                    g_el[(size_t)row * NHEAD + head] = pl[mt][rh];
                    g_er[(size_t)row * NHEAD + head] = pr[mt][rh];
                }
            }
    }
}

// ---------------- K2: warp-per-node edge softmax + SpMM (fp16 gather) --------
__device__ __forceinline__ float4 f4max(float4 a, float4 b) {
    return make_float4(fmaxf(a.x,b.x), fmaxf(a.y,b.y), fmaxf(a.z,b.z), fmaxf(a.w,b.w));
}
__device__ __forceinline__ float4 f4shfl_xor(float4 v, int off) {
    float4 r;
    r.x = __shfl_xor_sync(0xffffffffu, v.x, off);
    r.y = __shfl_xor_sync(0xffffffffu, v.y, off);
    r.z = __shfl_xor_sync(0xffffffffu, v.z, off);
    r.w = __shfl_xor_sync(0xffffffffu, v.w, off);
    return r;
}
__device__ __forceinline__ float4 f4exp(float4 v) {
    return make_float4(__expf(v.x), __expf(v.y), __expf(v.z), __expf(v.w));
}
__device__ __forceinline__ float f4sel(float4 v, int h) {
    return (h == 0) ? v.x : (h == 1) ? v.y : (h == 2) ? v.z : v.w;
}

__global__ __launch_bounds__(256) void agg_kernel(
    const int* __restrict__ row_ptr, const int* __restrict__ col_ind,
    float* __restrict__ out, int M)
{
    __shared__ __align__(16) float4 s_w[8][32];

    const int wid  = threadIdx.x >> 5;
    const int lane = threadIdx.x & 31;
    const int n = blockIdx.x * 8 + wid;
    if (n >= M) return;

    const int beg = row_ptr[n];
    const int deg = row_ptr[n + 1] - beg;
    const float4 el4 = *(const float4*)(g_el + (size_t)n * NHEAD);
    const int h = lane >> 3;          // 8 lanes per head, 8 cols per lane

    float acc[8];
#pragma unroll
    for (int q = 0; q < 8; q++) acc[q] = 0.f;
    float4 m4 = make_float4(-INFINITY,-INFINITY,-INFINITY,-INFINITY);
    float4 s4 = make_float4(0.f,0.f,0.f,0.f);

    for (int base = 0; base < deg; base += 32) {
        const int cnt = min(32, deg - base);
        int src = 0;
        float4 e4 = make_float4(-INFINITY,-INFINITY,-INFINITY,-INFINITY);
        if (lane < cnt) {
            src = col_ind[beg + base + lane];
            const float4 er4 = *(const float4*)(g_er + (size_t)src * NHEAD);
            float ex = er4.x + el4.x, ey = er4.y + el4.y;
            float ez = er4.z + el4.z, ew = er4.w + el4.w;
            e4.x = (ex > 0.f) ? ex : 0.2f * ex;
            e4.y = (ey > 0.f) ? ey : 0.2f * ey;
            e4.z = (ez > 0.f) ? ez : 0.2f * ez;
            e4.w = (ew > 0.f) ? ew : 0.2f * ew;
        }
        float4 cm = e4;
#pragma unroll
        for (int off = 16; off > 0; off >>= 1) cm = f4max(cm, f4shfl_xor(cm, off));
        const float4 nm = f4max(m4, cm);
        const float4 scale = f4exp(make_float4(m4.x-nm.x, m4.y-nm.y, m4.z-nm.z, m4.w-nm.w));
        m4 = nm;
        float4 w4 = f4exp(make_float4(e4.x-nm.x, e4.y-nm.y, e4.z-nm.z, e4.w-nm.w));
        float4 cs = w4;
#pragma unroll
        for (int off = 16; off > 0; off >>= 1) {
            const float4 o = f4shfl_xor(cs, off);
            cs.x += o.x; cs.y += o.y; cs.z += o.z; cs.w += o.w;
        }
        s4.x = s4.x * scale.x + cs.x; s4.y = s4.y * scale.y + cs.y;
        s4.z = s4.z * scale.z + cs.z; s4.w = s4.w * scale.w + cs.w;

        const float sc_h = f4sel(scale, h);
#pragma unroll
        for (int q = 0; q < 8; q++) acc[q] *= sc_h;

        s_w[wid][lane] = w4;
        __syncwarp();

#pragma unroll 4
        for (int j = 0; j < cnt; j++) {
            const int srcj = __shfl_sync(0xffffffffu, src, j);
            const float w = ((const float*)&s_w[wid][j])[h];
            const uint4 rv = ((const uint4*)(g_feat_h + (size_t)srcj * HD))[lane];
            const __half2* hp = (const __half2*)&rv;
#pragma unroll
            for (int q = 0; q < 4; q++) {
                const float2 f = __half22float2(hp[q]);
                acc[q*2]   = fmaf(w, f.x, acc[q*2]);
                acc[q*2+1] = fmaf(w, f.y, acc[q*2+1]);
            }
        }
        __syncwarp();
    }

    const float inv = (deg > 0) ? 1.0f / f4sel(s4, h) : 0.f;
#pragma unroll
    for (int q = 0; q < 8; q++) acc[q] *= inv;

    float4* o = (float4*)(out + (size_t)n * HD + lane * 8);
    o[0] = make_float4(acc[0], acc[1], acc[2], acc[3]);
    o[1] = make_float4(acc[4], acc[5], acc[6], acc[7]);
}

// ---------------- launch -----------------------------------------------------
extern "C" void kernel_launch(void* const* d_in, const int* in_sizes, int n_in,
                              void* d_out, int out_size)
{
    const int*   row_ptr = (const int*)d_in[0];
    const int*   col_ind = (const int*)d_in[1];
    const float* feat    = (const float*)d_in[2];
    const float* Wm      = (const float*)d_in[3];
    const float* attn_l  = (const float*)d_in[4];
    const float* attn_r  = (const float*)d_in[5];
    float* out = (float*)d_out;

    const int M = in_sizes[0] - 1;

    cudaFuncSetAttribute(gemm_mma_kernel,
                         cudaFuncAttributeMaxDynamicSharedMemorySize, SMEM_TOT);

    prep_w_kernel<<<64, 256>>>(Wm);
    gemm_mma_kernel<<<(M + 127) / 128, 512, SMEM_TOT>>>(feat, attn_l, attn_r, M);
    agg_kernel<<<(M + 7) / 8, 256>>>(row_ptr, col_ind, out, M);
}